// round 2
// baseline (speedup 1.0000x reference)
#include <cuda_runtime.h>

#define OUT_DIM 4096
#define IN_DIM  8192
#define ALPHA   0.001f
#define EPS     1e-12f

// Scan-kernel geometry
#define TROWS   32                    // rows per tile
#define NTILES  (OUT_DIM / TROWS)     // 128 tiles (scan chain length)
#define CCOLS   256                   // columns per chunk
#define NCHUNK  (IN_DIM / CCOLS)      // 32 column chunks
#define NSLOTS  (NTILES * NCHUNK)     // 4096 lookback slots

// Scratch (allocation-free): projection, normalized projection, lookback state
__device__ float g_y[OUT_DIM];
__device__ float g_yv[OUT_DIM];
__device__ float g_agg[NSLOTS * CCOLS];   // per-slot column aggregates   (4 MB)
__device__ float g_incl[NSLOTS * CCOLS];  // per-slot inclusive prefixes  (4 MB)
__device__ int   g_flag[NSLOTS];          // 0=none, 1=aggregate, 2=inclusive

__device__ __forceinline__ int ld_acquire(const int* p) {
    int v;
    asm volatile("ld.acquire.gpu.s32 %0, [%1];" : "=r"(v) : "l"(p));
    return v;
}
__device__ __forceinline__ void st_release(int* p, int v) {
    asm volatile("st.release.gpu.s32 [%0], %1;" :: "l"(p), "r"(v));
}

// ---------------------------------------------------------------------------
// Kernel 1: GEMV  y[r] = dot(W[r,:], x).  W streamed with evict-first hint.
// ---------------------------------------------------------------------------
__global__ void __launch_bounds__(256) gemv_kernel(
    const float* __restrict__ W, const float* __restrict__ x, float* __restrict__ y)
{
    const int row = blockIdx.x;
    const int tid = threadIdx.x;
    const float4* Wr = reinterpret_cast<const float4*>(W + (size_t)row * IN_DIM);
    const float4* x4 = reinterpret_cast<const float4*>(x);

    float s = 0.0f;
#pragma unroll
    for (int i = tid; i < IN_DIM / 4; i += 256) {
        float4 w = __ldcs(&Wr[i]);
        float4 v = x4[i];
        s += w.x * v.x + w.y * v.y + w.z * v.z + w.w * v.w;
    }
#pragma unroll
    for (int o = 16; o > 0; o >>= 1) s += __shfl_down_sync(0xFFFFFFFFu, s, o);

    __shared__ float red[8];
    if ((tid & 31) == 0) red[tid >> 5] = s;
    __syncthreads();
    if (tid < 8) {
        s = red[tid];
#pragma unroll
        for (int o = 4; o > 0; o >>= 1) s += __shfl_down_sync(0xFFu, s, o);
        if (tid == 0) y[row] = s;
    }
}

// ---------------------------------------------------------------------------
// Kernel 2: normalize y -> yv, emit y_n, and reset lookback flags for this run.
// ---------------------------------------------------------------------------
__global__ void __launch_bounds__(1024) normalize_kernel(
    const float* __restrict__ y, float* __restrict__ yv, float* __restrict__ out_yn)
{
    const int tid = threadIdx.x;

    // reset lookback flags (4096 ints)
#pragma unroll
    for (int i = tid; i < NSLOTS; i += 1024) g_flag[i] = 0;

    float ss = 0.0f;
#pragma unroll
    for (int i = tid; i < OUT_DIM; i += 1024) {
        float v = y[i];
        ss += v * v;
    }
#pragma unroll
    for (int o = 16; o > 0; o >>= 1) ss += __shfl_down_sync(0xFFFFFFFFu, ss, o);

    __shared__ float red[32];
    if ((tid & 31) == 0) red[tid >> 5] = ss;
    __syncthreads();
    __shared__ float s_inv;
    if (tid < 32) {
        float t = red[tid];
#pragma unroll
        for (int o = 16; o > 0; o >>= 1) t += __shfl_down_sync(0xFFFFFFFFu, t, o);
        if (tid == 0) s_inv = 1.0f / fmaxf(sqrtf(t), EPS);
    }
    __syncthreads();
    const float inv = s_inv;
#pragma unroll
    for (int i = tid; i < OUT_DIM; i += 1024) {
        float v = y[i] * inv;
        yv[i]     = v;
        out_yn[i] = v;
    }
}

// ---------------------------------------------------------------------------
// Kernel 3: single-pass decoupled-lookback column scan + Sanger apply.
// Block = (tile t = blockIdx.x of 32 rows, column chunk cc = blockIdx.y of 256).
// W chunk is held in shared across the lookback, so W is read exactly once.
// ---------------------------------------------------------------------------
__global__ void __launch_bounds__(256) sanger_scan_kernel(
    const float* __restrict__ W, const float* __restrict__ x,
    const float* __restrict__ yv, float* __restrict__ Wout)
{
    __shared__ float Wsh[TROWS][CCOLS];   // 32 KB
    __shared__ float yvs[TROWS];

    const int tid  = threadIdx.x;          // == column index c within chunk
    const int t    = blockIdx.x;           // tile index (scan dimension)
    const int cc   = blockIdx.y;           // column chunk
    const int row0 = t * TROWS;
    const int col0 = cc * CCOLS;
    const int slotbase = cc * NTILES;      // chain base for this column chunk
    const int slot     = slotbase + t;

    // stage yv slice
    if (tid < TROWS) yvs[tid] = yv[row0 + tid];

    // Load W chunk: 32 rows x 256 cols = 2048 float4, 8 per thread, coalesced.
    {
        const int c4 = (tid & 63) * 4;     // float4 column offset within row
        const int jb = tid >> 6;           // 0..3
#pragma unroll
        for (int k = 0; k < 8; ++k) {
            const int j = k * 4 + jb;
            float4 w = __ldcs(reinterpret_cast<const float4*>(
                W + (size_t)(row0 + j) * IN_DIM + col0 + c4));
            *reinterpret_cast<float4*>(&Wsh[j][c4]) = w;
        }
    }
    __syncthreads();

    // Column partial for this tile: P[c] = sum_j Wsh[j][c] * yv[row0+j]
    float P = 0.0f;
#pragma unroll
    for (int j = 0; j < TROWS; ++j) P += Wsh[j][tid] * yvs[j];

    // Publish aggregate (tile 0 publishes inclusive directly)
    g_agg[(size_t)slot * CCOLS + tid] = P;
    float excl = 0.0f;
    if (t == 0) {
        g_incl[(size_t)slot * CCOLS + tid] = P;
        __threadfence();
        __syncthreads();
        if (tid == 0) st_release(&g_flag[slot], 2);
    } else {
        __threadfence();
        __syncthreads();
        if (tid == 0) st_release(&g_flag[slot], 1);

        // Decoupled lookback (each thread walks its own column; flag uniform-ish)
        int p = t - 1;
        while (p >= 0) {
            int f;
            do { f = ld_acquire(&g_flag[slotbase + p]); } while (f == 0);
            if (f == 2) { excl += g_incl[(size_t)(slotbase + p) * CCOLS + tid]; break; }
            excl += g_agg[(size_t)(slotbase + p) * CCOLS + tid];
            --p;
        }

        // Publish our inclusive prefix
        g_incl[(size_t)slot * CCOLS + tid] = excl + P;
        __threadfence();
        __syncthreads();
        if (tid == 0) st_release(&g_flag[slot], 2);
    }

    // Apply Sanger update and stream out (W never re-read from global)
    const float xc = x[col0 + tid];
    float s_run = excl;
#pragma unroll
    for (int j = 0; j < TROWS; ++j) {
        const float w  = Wsh[j][tid];
        const float yj = yvs[j];
        s_run += w * yj;                              // inclusive running sum
        __stcs(Wout + (size_t)(row0 + j) * IN_DIM + col0 + tid,
               w + ALPHA * yj * (xc - s_run));
    }
}

// ---------------------------------------------------------------------------
extern "C" void kernel_launch(void* const* d_in, const int* in_sizes, int n_in,
                              void* d_out, int out_size)
{
    const float* x = (const float*)d_in[0];  // [1, 8192]
    const float* W = (const float*)d_in[1];  // [4096, 8192]
    float* out = (float*)d_out;              // [4096 y_n] ++ [4096*8192 W_new]

    float* y  = nullptr;
    float* yv = nullptr;
    cudaGetSymbolAddress((void**)&y,  g_y);
    cudaGetSymbolAddress((void**)&yv, g_yv);

    gemv_kernel<<<OUT_DIM, 256>>>(W, x, y);
    normalize_kernel<<<1, 1024>>>(y, yv, out);

    dim3 grid(NTILES, NCHUNK);               // bid = t + cc*NTILES: t ascends first
    sanger_scan_kernel<<<grid, 256>>>(W, x, yv, out + OUT_DIM);
}

// round 3
// speedup vs baseline: 1.3438x; 1.3438x over previous
#include <cuda_runtime.h>

#define OUT_DIM 4096
#define IN_DIM  8192
#define ALPHA   0.001f
#define EPS     1e-12f

// Scan-kernel geometry: tall narrow tiles -> short lookback chains
#define TROWS   256                   // rows per tile
#define NTILES  (OUT_DIM / TROWS)     // 16 tiles per chain
#define CCOLS   32                    // columns per chunk (lane <-> column)
#define NCHUNK  (IN_DIM / CCOLS)      // 256 independent chains
#define NSLOTS  (NTILES * NCHUNK)     // 4096 slots

// Scratch (allocation-free)
__device__ float g_y[OUT_DIM];
__device__ float g_yv[OUT_DIM];
__device__ float g_agg[NSLOTS * CCOLS];   // 512 KB
__device__ float g_incl[NSLOTS * CCOLS];  // 512 KB
__device__ int   g_flag[NSLOTS];          // 0=none, 1=aggregate, 2=inclusive

__device__ __forceinline__ int ld_acquire(const int* p) {
    int v;
    asm volatile("ld.acquire.gpu.s32 %0, [%1];" : "=r"(v) : "l"(p));
    return v;
}
__device__ __forceinline__ void st_release(int* p, int v) {
    asm volatile("st.release.gpu.s32 [%0], %1;" :: "l"(p), "r"(v));
}

// ---------------------------------------------------------------------------
// Kernel 1: GEMV  y[r] = dot(W[r,:], x)
// ---------------------------------------------------------------------------
__global__ void __launch_bounds__(256) gemv_kernel(
    const float* __restrict__ W, const float* __restrict__ x, float* __restrict__ y)
{
    const int row = blockIdx.x;
    const int tid = threadIdx.x;
    const float4* Wr = reinterpret_cast<const float4*>(W + (size_t)row * IN_DIM);
    const float4* x4 = reinterpret_cast<const float4*>(x);

    float s = 0.0f;
#pragma unroll
    for (int i = tid; i < IN_DIM / 4; i += 256) {
        float4 w = __ldcs(&Wr[i]);
        float4 v = x4[i];
        s += w.x * v.x + w.y * v.y + w.z * v.z + w.w * v.w;
    }
#pragma unroll
    for (int o = 16; o > 0; o >>= 1) s += __shfl_down_sync(0xFFFFFFFFu, s, o);

    __shared__ float red[8];
    if ((tid & 31) == 0) red[tid >> 5] = s;
    __syncthreads();
    if (tid < 8) {
        s = red[tid];
#pragma unroll
        for (int o = 4; o > 0; o >>= 1) s += __shfl_down_sync(0xFFu, s, o);
        if (tid == 0) y[row] = s;
    }
}

// ---------------------------------------------------------------------------
// Kernel 2: normalize y -> yv, emit y_n, reset lookback flags (per replay)
// ---------------------------------------------------------------------------
__global__ void __launch_bounds__(1024) normalize_kernel(
    const float* __restrict__ y, float* __restrict__ yv, float* __restrict__ out_yn)
{
    const int tid = threadIdx.x;

#pragma unroll
    for (int i = tid; i < NSLOTS; i += 1024) g_flag[i] = 0;

    float ss = 0.0f;
#pragma unroll
    for (int i = tid; i < OUT_DIM; i += 1024) {
        float v = y[i];
        ss += v * v;
    }
#pragma unroll
    for (int o = 16; o > 0; o >>= 1) ss += __shfl_down_sync(0xFFFFFFFFu, ss, o);

    __shared__ float red[32];
    if ((tid & 31) == 0) red[tid >> 5] = ss;
    __syncthreads();
    __shared__ float s_inv;
    if (tid < 32) {
        float t = red[tid];
#pragma unroll
        for (int o = 16; o > 0; o >>= 1) t += __shfl_down_sync(0xFFFFFFFFu, t, o);
        if (tid == 0) s_inv = 1.0f / fmaxf(sqrtf(t), EPS);
    }
    __syncthreads();
    const float inv = s_inv;
#pragma unroll
    for (int i = tid; i < OUT_DIM; i += 1024) {
        float v = y[i] * inv;
        yv[i]     = v;
        out_yn[i] = v;
    }
}

// ---------------------------------------------------------------------------
// Kernel 3: single-pass decoupled-lookback scan + Sanger apply.
// Tile = 256 rows x 32 cols per block. 8 warps x 32-row segments.
// Chain length 16; lookback by warp 0 only, 128 B per step.
// ---------------------------------------------------------------------------
__global__ void __launch_bounds__(256) sanger_scan_kernel(
    const float* __restrict__ W, const float* __restrict__ x,
    const float* __restrict__ yv, float* __restrict__ Wout)
{
    __shared__ float Wsh[TROWS][CCOLS];    // 32 KB
    __shared__ float yvs[TROWS];           // 1 KB
    __shared__ float s_part[8][CCOLS];     // per-warp-segment column partials
    __shared__ float excl_sh[CCOLS];       // cross-tile exclusive prefix

    const int tid  = threadIdx.x;
    const int l    = tid & 31;             // lane <-> column
    const int w    = tid >> 5;             // warp <-> 32-row segment
    const int t    = blockIdx.x;           // tile (scan dim)
    const int cc   = blockIdx.y;           // chain id
    const int row0 = t * TROWS;
    const int col0 = cc * CCOLS;
    const int slotbase = cc * NTILES;
    const int slot     = slotbase + t;

    yvs[tid] = yv[row0 + tid];

    // Load W tile: each warp loads its 32 rows; 128 B coalesced per instr.
    {
        const float* Wp = W + (size_t)(row0 + w * 32) * IN_DIM + col0 + l;
#pragma unroll
        for (int j = 0; j < 32; ++j)
            Wsh[w * 32 + j][l] = __ldcs(Wp + (size_t)j * IN_DIM);
    }
    __syncthreads();

    // Per-segment column partial
    float P = 0.0f;
#pragma unroll
    for (int j = 0; j < 32; ++j)
        P += Wsh[w * 32 + j][l] * yvs[w * 32 + j];
    s_part[w][l] = P;
    __syncthreads();

    // Warp 0: publish aggregate, lookback, publish inclusive
    if (w == 0) {
        float agg = 0.0f;
#pragma unroll
        for (int ww = 0; ww < 8; ++ww) agg += s_part[ww][l];

        g_agg[(size_t)slot * CCOLS + l] = agg;
        __syncwarp();
        if (l == 0) { __threadfence(); st_release(&g_flag[slot], (t == 0) ? 1 : 1); }

        float e = 0.0f;
        if (t > 0) {
            int p = t - 1;
            while (true) {
                int f;
                do { f = ld_acquire(&g_flag[slotbase + p]); } while (f == 0);
                if (f == 2) { e += g_incl[(size_t)(slotbase + p) * CCOLS + l]; break; }
                e += g_agg[(size_t)(slotbase + p) * CCOLS + l];
                if (--p < 0) break;
            }
        }
        excl_sh[l] = e;
        g_incl[(size_t)slot * CCOLS + l] = e + agg;
        __syncwarp();
        if (l == 0) { __threadfence(); st_release(&g_flag[slot], 2); }
    }
    __syncthreads();

    // In-block segment exclusive prefix + apply
    float run = excl_sh[l];
#pragma unroll
    for (int ww = 0; ww < 8; ++ww)
        if (ww < w) run += s_part[ww][l];

    const float xc = x[col0 + l];
    {
        float* Op = Wout + (size_t)(row0 + w * 32) * IN_DIM + col0 + l;
#pragma unroll
        for (int j = 0; j < 32; ++j) {
            const int r = w * 32 + j;
            const float wv = Wsh[r][l];
            const float yj = yvs[r];
            run += wv * yj;
            __stcs(Op + (size_t)j * IN_DIM, wv + ALPHA * yj * (xc - run));
        }
    }
}

// ---------------------------------------------------------------------------
extern "C" void kernel_launch(void* const* d_in, const int* in_sizes, int n_in,
                              void* d_out, int out_size)
{
    const float* x = (const float*)d_in[0];  // [1, 8192]
    const float* W = (const float*)d_in[1];  // [4096, 8192]
    float* out = (float*)d_out;              // [4096 y_n] ++ [4096*8192 W_new]

    float* y  = nullptr;
    float* yv = nullptr;
    cudaGetSymbolAddress((void**)&y,  g_y);
    cudaGetSymbolAddress((void**)&yv, g_yv);

    gemv_kernel<<<OUT_DIM, 256>>>(W, x, y);
    normalize_kernel<<<1, 1024>>>(y, yv, out);

    dim3 grid(NTILES, NCHUNK);   // tiles ascend fastest within each chain
    sanger_scan_kernel<<<grid, 256>>>(W, x, yv, out + OUT_DIM);
}

// round 4
// speedup vs baseline: 1.4159x; 1.0536x over previous
#include <cuda_runtime.h>

#define OUT_DIM 4096
#define IN_DIM  8192
#define ALPHA   0.001f
#define EPS     1e-12f

// Scan-kernel geometry: 128x128 tiles, float4 access, chains of 32
#define TROWS   128
#define NTILES  (OUT_DIM / TROWS)     // 32 tiles per chain
#define CCOLS   128
#define NCHUNK  (IN_DIM / CCOLS)      // 64 independent chains
#define NSLOTS  (NTILES * NCHUNK)     // 2048 slots

// Scratch (allocation-free)
__device__ float g_y[OUT_DIM];
__device__ float g_yv[OUT_DIM];
__device__ float g_agg[NSLOTS * CCOLS];   // 1 MB
__device__ float g_incl[NSLOTS * CCOLS];  // 1 MB
__device__ int   g_flag[NSLOTS];

__device__ __forceinline__ int ld_acquire(const int* p) {
    int v;
    asm volatile("ld.acquire.gpu.s32 %0, [%1];" : "=r"(v) : "l"(p));
    return v;
}
__device__ __forceinline__ void st_release(int* p, int v) {
    asm volatile("st.release.gpu.s32 [%0], %1;" :: "l"(p), "r"(v));
}

// ---------------------------------------------------------------------------
// Kernel 1: GEMV  y[r] = dot(W[r,:], x)
// ---------------------------------------------------------------------------
__global__ void __launch_bounds__(256) gemv_kernel(
    const float* __restrict__ W, const float* __restrict__ x, float* __restrict__ y)
{
    const int row = blockIdx.x;
    const int tid = threadIdx.x;
    const float4* Wr = reinterpret_cast<const float4*>(W + (size_t)row * IN_DIM);
    const float4* x4 = reinterpret_cast<const float4*>(x);

    float s = 0.0f;
#pragma unroll
    for (int i = tid; i < IN_DIM / 4; i += 256) {
        float4 w = __ldcs(&Wr[i]);
        float4 v = x4[i];
        s += w.x * v.x + w.y * v.y + w.z * v.z + w.w * v.w;
    }
#pragma unroll
    for (int o = 16; o > 0; o >>= 1) s += __shfl_down_sync(0xFFFFFFFFu, s, o);

    __shared__ float red[8];
    if ((tid & 31) == 0) red[tid >> 5] = s;
    __syncthreads();
    if (tid < 8) {
        s = red[tid];
#pragma unroll
        for (int o = 4; o > 0; o >>= 1) s += __shfl_down_sync(0xFFu, s, o);
        if (tid == 0) y[row] = s;
    }
}

// ---------------------------------------------------------------------------
// Kernel 2: normalize y -> yv, emit y_n, reset lookback flags (per replay)
// ---------------------------------------------------------------------------
__global__ void __launch_bounds__(1024) normalize_kernel(
    const float* __restrict__ y, float* __restrict__ yv, float* __restrict__ out_yn)
{
    const int tid = threadIdx.x;

#pragma unroll
    for (int i = tid; i < NSLOTS; i += 1024) g_flag[i] = 0;

    float ss = 0.0f;
#pragma unroll
    for (int i = tid; i < OUT_DIM; i += 1024) {
        float v = y[i];
        ss += v * v;
    }
#pragma unroll
    for (int o = 16; o > 0; o >>= 1) ss += __shfl_down_sync(0xFFFFFFFFu, ss, o);

    __shared__ float red[32];
    if ((tid & 31) == 0) red[tid >> 5] = ss;
    __syncthreads();
    __shared__ float s_inv;
    if (tid < 32) {
        float t = red[tid];
#pragma unroll
        for (int o = 16; o > 0; o >>= 1) t += __shfl_down_sync(0xFFFFFFFFu, t, o);
        if (tid == 0) s_inv = 1.0f / fmaxf(sqrtf(t), EPS);
    }
    __syncthreads();
    const float inv = s_inv;
#pragma unroll
    for (int i = tid; i < OUT_DIM; i += 1024) {
        float v = y[i] * inv;
        yv[i]     = v;
        out_yn[i] = v;
    }
}

// ---------------------------------------------------------------------------
// Kernel 3: single-pass decoupled-lookback scan + Sanger apply.
// Tile 128 rows x 128 cols. 8 warps x 16-row segments; lane <-> 4 columns.
// All global W traffic is float4 (512 B contiguous per warp per row).
// ---------------------------------------------------------------------------
__global__ void __launch_bounds__(256) sanger_scan_kernel(
    const float* __restrict__ W, const float* __restrict__ x,
    const float* __restrict__ yv, float* __restrict__ Wout)
{
    __shared__ float4 Wsh[TROWS][CCOLS / 4];   // 64 KB
    __shared__ float  yvs[TROWS];              // 512 B
    __shared__ float4 s_part[8][CCOLS / 4];    // 4 KB
    __shared__ float4 excl_sh[CCOLS / 4];      // 512 B

    const int tid  = threadIdx.x;
    const int l    = tid & 31;                 // lane -> float4 column group
    const int w    = tid >> 5;                 // warp -> 16-row segment
    const int t    = blockIdx.x;               // tile (scan dim)
    const int cc   = blockIdx.y;               // chain id
    const int row0 = t * TROWS;
    const int col0 = cc * CCOLS;
    const int slotbase = cc * NTILES;
    const int slot     = slotbase + t;

    if (tid < TROWS) yvs[tid] = yv[row0 + tid];

    // Load W tile: warp w loads rows w*16..w*16+15, lane l -> cols l*4..l*4+3
    {
        const float4* Wp = reinterpret_cast<const float4*>(
            W + (size_t)(row0 + w * 16) * IN_DIM + col0) + l;
#pragma unroll
        for (int j = 0; j < 16; ++j)
            Wsh[w * 16 + j][l] = __ldcs(Wp + (size_t)j * (IN_DIM / 4));
    }
    __syncthreads();

    // Per-segment column partials (4 independent accumulators per thread)
    float4 P = make_float4(0.f, 0.f, 0.f, 0.f);
#pragma unroll
    for (int j = 0; j < 16; ++j) {
        const float4 wv = Wsh[w * 16 + j][l];
        const float  yj = yvs[w * 16 + j];
        P.x += wv.x * yj; P.y += wv.y * yj; P.z += wv.z * yj; P.w += wv.w * yj;
    }
    s_part[w][l] = P;
    __syncthreads();

    // Warp 0: publish aggregate, lookback, publish inclusive
    if (w == 0) {
        float4 agg = make_float4(0.f, 0.f, 0.f, 0.f);
#pragma unroll
        for (int ww = 0; ww < 8; ++ww) {
            const float4 p = s_part[ww][l];
            agg.x += p.x; agg.y += p.y; agg.z += p.z; agg.w += p.w;
        }

        float4* aggp  = reinterpret_cast<float4*>(g_agg  + (size_t)slot * CCOLS);
        float4* inclp = reinterpret_cast<float4*>(g_incl + (size_t)slot * CCOLS);

        float4 e = make_float4(0.f, 0.f, 0.f, 0.f);
        if (t == 0) {
            inclp[l] = agg;
            __syncwarp();
            if (l == 0) { __threadfence(); st_release(&g_flag[slot], 2); }
        } else {
            aggp[l] = agg;
            __syncwarp();
            if (l == 0) { __threadfence(); st_release(&g_flag[slot], 1); }

            int p = t - 1;
            while (true) {
                int f;
                do { f = ld_acquire(&g_flag[slotbase + p]); } while (f == 0);
                const float4* src = reinterpret_cast<const float4*>(
                    ((f == 2) ? g_incl : g_agg) + (size_t)(slotbase + p) * CCOLS);
                const float4 v = src[l];
                e.x += v.x; e.y += v.y; e.z += v.z; e.w += v.w;
                if (f == 2 || --p < 0) break;
            }
            float4 inc = make_float4(e.x + agg.x, e.y + agg.y, e.z + agg.z, e.w + agg.w);
            inclp[l] = inc;
            __syncwarp();
            if (l == 0) { __threadfence(); st_release(&g_flag[slot], 2); }
        }
        excl_sh[l] = e;
    }
    __syncthreads();

    // In-block segment exclusive prefix
    float4 run = excl_sh[l];
#pragma unroll
    for (int ww = 0; ww < 8; ++ww)
        if (ww < w) {
            const float4 p = s_part[ww][l];
            run.x += p.x; run.y += p.y; run.z += p.z; run.w += p.w;
        }

    // Apply + streaming store
    const float4 xc = reinterpret_cast<const float4*>(x + col0)[l];
    {
        float4* Op = reinterpret_cast<float4*>(
            Wout + (size_t)(row0 + w * 16) * IN_DIM + col0) + l;
#pragma unroll
        for (int j = 0; j < 16; ++j) {
            const int r = w * 16 + j;
            const float4 wv = Wsh[r][l];
            const float  yj = yvs[r];
            run.x += wv.x * yj; run.y += wv.y * yj;
            run.z += wv.z * yj; run.w += wv.w * yj;
            float4 o;
            const float a = ALPHA * yj;
            o.x = wv.x + a * (xc.x - run.x);
            o.y = wv.y + a * (xc.y - run.y);
            o.z = wv.z + a * (xc.z - run.z);
            o.w = wv.w + a * (xc.w - run.w);
            __stcs(Op + (size_t)j * (IN_DIM / 4), o);
        }
    }
}

// ---------------------------------------------------------------------------
extern "C" void kernel_launch(void* const* d_in, const int* in_sizes, int n_in,
                              void* d_out, int out_size)
{
    const float* x = (const float*)d_in[0];  // [1, 8192]
    const float* W = (const float*)d_in[1];  // [4096, 8192]
    float* out = (float*)d_out;              // [4096 y_n] ++ [4096*8192 W_new]

    float* y  = nullptr;
    float* yv = nullptr;
    cudaGetSymbolAddress((void**)&y,  g_y);
    cudaGetSymbolAddress((void**)&yv, g_yv);

    gemv_kernel<<<OUT_DIM, 256>>>(W, x, y);
    normalize_kernel<<<1, 1024>>>(y, yv, out);

    dim3 grid(NTILES, NCHUNK);   // tiles ascend fastest within each chain
    sanger_scan_kernel<<<grid, 256>>>(W, x, yv, out + OUT_DIM);
}

// round 5
// speedup vs baseline: 1.8726x; 1.3226x over previous
#include <cuda_runtime.h>

#define OUT_DIM 4096
#define IN_DIM  8192
#define ALPHA   0.001f
#define EPS     1e-12f

// Scan-kernel geometry: 128x128 tiles, float4 access, chains of 32
#define TROWS   128
#define NTILES  (OUT_DIM / TROWS)     // 32 tiles per chain
#define CCOLS   128
#define NCHUNK  (IN_DIM / CCOLS)      // 64 independent chains
#define NSLOTS  (NTILES * NCHUNK)     // 2048 slots

// Scratch (allocation-free)
__device__ float g_y[OUT_DIM];
__device__ float g_yv[OUT_DIM];
__device__ float g_agg[NSLOTS * CCOLS];   // 1 MB
__device__ float g_incl[NSLOTS * CCOLS];  // 1 MB
__device__ int   g_flag[NSLOTS];

__device__ __forceinline__ int ld_acquire(const int* p) {
    int v;
    asm volatile("ld.acquire.gpu.s32 %0, [%1];" : "=r"(v) : "l"(p));
    return v;
}
__device__ __forceinline__ void st_release(int* p, int v) {
    asm volatile("st.release.gpu.s32 [%0], %1;" :: "l"(p), "r"(v));
}

// ---------------------------------------------------------------------------
// Kernel 1: GEMV  y[r] = dot(W[r,:], x)
// ---------------------------------------------------------------------------
__global__ void __launch_bounds__(256) gemv_kernel(
    const float* __restrict__ W, const float* __restrict__ x, float* __restrict__ y)
{
    const int row = blockIdx.x;
    const int tid = threadIdx.x;
    const float4* Wr = reinterpret_cast<const float4*>(W + (size_t)row * IN_DIM);
    const float4* x4 = reinterpret_cast<const float4*>(x);

    float s = 0.0f;
#pragma unroll
    for (int i = tid; i < IN_DIM / 4; i += 256) {
        float4 w = __ldcs(&Wr[i]);
        float4 v = x4[i];
        s += w.x * v.x + w.y * v.y + w.z * v.z + w.w * v.w;
    }
#pragma unroll
    for (int o = 16; o > 0; o >>= 1) s += __shfl_down_sync(0xFFFFFFFFu, s, o);

    __shared__ float red[8];
    if ((tid & 31) == 0) red[tid >> 5] = s;
    __syncthreads();
    if (tid < 8) {
        s = red[tid];
#pragma unroll
        for (int o = 4; o > 0; o >>= 1) s += __shfl_down_sync(0xFFu, s, o);
        if (tid == 0) y[row] = s;
    }
}

// ---------------------------------------------------------------------------
// Kernel 2: normalize y -> yv, emit y_n, reset lookback flags (per replay)
// ---------------------------------------------------------------------------
__global__ void __launch_bounds__(1024) normalize_kernel(
    const float* __restrict__ y, float* __restrict__ yv, float* __restrict__ out_yn)
{
    const int tid = threadIdx.x;

#pragma unroll
    for (int i = tid; i < NSLOTS; i += 1024) g_flag[i] = 0;

    float ss = 0.0f;
#pragma unroll
    for (int i = tid; i < OUT_DIM; i += 1024) {
        float v = y[i];
        ss += v * v;
    }
#pragma unroll
    for (int o = 16; o > 0; o >>= 1) ss += __shfl_down_sync(0xFFFFFFFFu, ss, o);

    __shared__ float red[32];
    if ((tid & 31) == 0) red[tid >> 5] = ss;
    __syncthreads();
    __shared__ float s_inv;
    if (tid < 32) {
        float t = red[tid];
#pragma unroll
        for (int o = 16; o > 0; o >>= 1) t += __shfl_down_sync(0xFFFFFFFFu, t, o);
        if (tid == 0) s_inv = 1.0f / fmaxf(sqrtf(t), EPS);
    }
    __syncthreads();
    const float inv = s_inv;
#pragma unroll
    for (int i = tid; i < OUT_DIM; i += 1024) {
        float v = y[i] * inv;
        yv[i]     = v;
        out_yn[i] = v;
    }
}

// ---------------------------------------------------------------------------
// Kernel 3: single-pass decoupled-lookback scan + Sanger apply.
// Tile 128 rows x 128 cols. 8 warps x 16-row segments; lane <-> 4 columns.
// Grid ordering: scan dim t ascends SLOWEST so predecessors are (nearly)
// always complete when a block looks back -> lookback depth ~1.
// ---------------------------------------------------------------------------
__global__ void __launch_bounds__(256) sanger_scan_kernel(
    const float* __restrict__ W, const float* __restrict__ x,
    const float* __restrict__ yv, float* __restrict__ Wout)
{
    __shared__ float4 Wsh[TROWS][CCOLS / 4];   // 64 KB
    __shared__ float  yvs[TROWS];              // 512 B
    __shared__ float4 s_part[8][CCOLS / 4];    // 4 KB
    __shared__ float4 excl_sh[CCOLS / 4];      // 512 B

    const int tid  = threadIdx.x;
    const int l    = tid & 31;                 // lane -> float4 column group
    const int w    = tid >> 5;                 // warp -> 16-row segment
    const int cc   = blockIdx.x;               // chain id (fastest)
    const int t    = blockIdx.y;               // tile / scan dim (slowest)
    const int row0 = t * TROWS;
    const int col0 = cc * CCOLS;
    const int slotbase = cc * NTILES;
    const int slot     = slotbase + t;

    if (tid < TROWS) yvs[tid] = yv[row0 + tid];

    // Load W tile: warp w loads rows w*16..w*16+15, lane l -> cols l*4..l*4+3
    {
        const float4* Wp = reinterpret_cast<const float4*>(
            W + (size_t)(row0 + w * 16) * IN_DIM + col0) + l;
#pragma unroll
        for (int j = 0; j < 16; ++j)
            Wsh[w * 16 + j][l] = __ldcs(Wp + (size_t)j * (IN_DIM / 4));
    }
    __syncthreads();

    // Per-segment column partials (4 independent accumulators per thread)
    float4 P = make_float4(0.f, 0.f, 0.f, 0.f);
#pragma unroll
    for (int j = 0; j < 16; ++j) {
        const float4 wv = Wsh[w * 16 + j][l];
        const float  yj = yvs[w * 16 + j];
        P.x += wv.x * yj; P.y += wv.y * yj; P.z += wv.z * yj; P.w += wv.w * yj;
    }
    s_part[w][l] = P;
    __syncthreads();

    // Warp 0: publish aggregate, lookback, publish inclusive
    if (w == 0) {
        float4 agg = make_float4(0.f, 0.f, 0.f, 0.f);
#pragma unroll
        for (int ww = 0; ww < 8; ++ww) {
            const float4 p = s_part[ww][l];
            agg.x += p.x; agg.y += p.y; agg.z += p.z; agg.w += p.w;
        }

        float4* aggp  = reinterpret_cast<float4*>(g_agg  + (size_t)slot * CCOLS);
        float4* inclp = reinterpret_cast<float4*>(g_incl + (size_t)slot * CCOLS);

        float4 e = make_float4(0.f, 0.f, 0.f, 0.f);
        if (t == 0) {
            inclp[l] = agg;
            __syncwarp();
            if (l == 0) { __threadfence(); st_release(&g_flag[slot], 2); }
        } else {
            aggp[l] = agg;
            __syncwarp();
            if (l == 0) { __threadfence(); st_release(&g_flag[slot], 1); }

            int p = t - 1;
            while (true) {
                int f;
                do { f = ld_acquire(&g_flag[slotbase + p]); } while (f == 0);
                const float4* src = reinterpret_cast<const float4*>(
                    ((f == 2) ? g_incl : g_agg) + (size_t)(slotbase + p) * CCOLS);
                const float4 v = src[l];
                e.x += v.x; e.y += v.y; e.z += v.z; e.w += v.w;
                if (f == 2 || --p < 0) break;
            }
            float4 inc = make_float4(e.x + agg.x, e.y + agg.y, e.z + agg.z, e.w + agg.w);
            inclp[l] = inc;
            __syncwarp();
            if (l == 0) { __threadfence(); st_release(&g_flag[slot], 2); }
        }
        excl_sh[l] = e;
    }
    __syncthreads();

    // In-block segment exclusive prefix
    float4 run = excl_sh[l];
#pragma unroll
    for (int ww = 0; ww < 8; ++ww)
        if (ww < w) {
            const float4 p = s_part[ww][l];
            run.x += p.x; run.y += p.y; run.z += p.z; run.w += p.w;
        }

    // Apply + streaming store
    const float4 xc = reinterpret_cast<const float4*>(x + col0)[l];
    {
        float4* Op = reinterpret_cast<float4*>(
            Wout + (size_t)(row0 + w * 16) * IN_DIM + col0) + l;
#pragma unroll
        for (int j = 0; j < 16; ++j) {
            const int r = w * 16 + j;
            const float4 wv = Wsh[r][l];
            const float  yj = yvs[r];
            run.x += wv.x * yj; run.y += wv.y * yj;
            run.z += wv.z * yj; run.w += wv.w * yj;
            float4 o;
            const float a = ALPHA * yj;
            o.x = wv.x + a * (xc.x - run.x);
            o.y = wv.y + a * (xc.y - run.y);
            o.z = wv.z + a * (xc.z - run.z);
            o.w = wv.w + a * (xc.w - run.w);
            __stcs(Op + (size_t)j * (IN_DIM / 4), o);
        }
    }
}

// ---------------------------------------------------------------------------
extern "C" void kernel_launch(void* const* d_in, const int* in_sizes, int n_in,
                              void* d_out, int out_size)
{
    const float* x = (const float*)d_in[0];  // [1, 8192]
    const float* W = (const float*)d_in[1];  // [4096, 8192]
    float* out = (float*)d_out;              // [4096 y_n] ++ [4096*8192 W_new]

    float* y  = nullptr;
    float* yv = nullptr;
    cudaGetSymbolAddress((void**)&y,  g_y);
    cudaGetSymbolAddress((void**)&yv, g_yv);

    gemv_kernel<<<OUT_DIM, 256>>>(W, x, y);
    normalize_kernel<<<1, 1024>>>(y, yv, out);

    dim3 grid(NCHUNK, NTILES);   // chain id fastest; scan dim t SLOWEST
    sanger_scan_kernel<<<grid, 256>>>(W, x, yv, out + OUT_DIM);
}